// round 1
// baseline (speedup 1.0000x reference)
#include <cuda_runtime.h>
#include <cuda_bf16.h>
#include <cstdint>

// Problem constants
#define B_ 4
#define S_ 1024
#define D_ 1024
#define H_ 16
#define DK_ 64
#define M_TOT (B_ * S_)   // 4096

// Scratch for projected Q, K, V (allocation-free rule: __device__ globals)
__device__ float g_Q[M_TOT * D_];
__device__ float g_K[M_TOT * D_];
__device__ float g_V[M_TOT * D_];

// ---------------------------------------------------------------------------
// Projection GEMM: C[M,N] = X[M,K] @ W[N,K]^T + bias[N]
// M=4096, N=K=1024. 128x128 block tile, BK=16, 256 threads, 8x8 per thread
// (2x2 groups of 4x4 so smem reads are conflict-free float4s).
// blockIdx.z selects (X, W, bias, Out) for q / k / v.
// ---------------------------------------------------------------------------
#define GBM 128
#define GBN 128
#define GBK 16

__global__ __launch_bounds__(256, 2)
void qkv_proj_kernel(const float* __restrict__ Xq,
                     const float* __restrict__ Xk,
                     const float* __restrict__ Xv,
                     const float* __restrict__ Wq, const float* __restrict__ bq,
                     const float* __restrict__ Wk, const float* __restrict__ bk,
                     const float* __restrict__ Wv, const float* __restrict__ bv) {
    const int N = D_, K = D_;

    const float* X;
    const float* W;
    const float* bias;
    float* Out;
    if (blockIdx.z == 0)      { X = Xq; W = Wq; bias = bq; Out = g_Q; }
    else if (blockIdx.z == 1) { X = Xk; W = Wk; bias = bk; Out = g_K; }
    else                      { X = Xv; W = Wv; bias = bv; Out = g_V; }

    __shared__ float As[GBK][GBM + 4];   // [k][m], +4 pad keeps float4 alignment
    __shared__ float Bs[GBK][GBN + 4];   // [k][n]

    const int t  = threadIdx.x;
    const int tx = t & 15;        // 0..15 -> column groups
    const int ty = t >> 4;        // 0..15 -> row groups
    const int m0 = blockIdx.y * GBM;
    const int n0 = blockIdx.x * GBN;

    float acc[8][8];
    #pragma unroll
    for (int i = 0; i < 8; i++)
        #pragma unroll
        for (int j = 0; j < 8; j++) acc[i][j] = 0.f;

    for (int k0 = 0; k0 < K; k0 += GBK) {
        // Load A and W tiles, transposed into [k][m] layout.
        // 128 rows x 16 k = 512 float4 jobs per tile; each thread does 2.
        #pragma unroll
        for (int i = 0; i < 2; i++) {
            int f  = t + i * 256;         // 0..511
            int m  = f >> 2;              // 0..127
            int kq = (f & 3) * 4;         // 0,4,8,12
            float4 a = *(const float4*)&X[(size_t)(m0 + m) * K + k0 + kq];
            As[kq + 0][m] = a.x; As[kq + 1][m] = a.y;
            As[kq + 2][m] = a.z; As[kq + 3][m] = a.w;
            float4 w = *(const float4*)&W[(size_t)(n0 + m) * K + k0 + kq];
            Bs[kq + 0][m] = w.x; Bs[kq + 1][m] = w.y;
            Bs[kq + 2][m] = w.z; Bs[kq + 3][m] = w.w;
        }
        __syncthreads();

        #pragma unroll
        for (int kk = 0; kk < GBK; kk++) {
            float ra[8], rb[8];
            *(float4*)&ra[0] = *(const float4*)&As[kk][ty * 4];
            *(float4*)&ra[4] = *(const float4*)&As[kk][64 + ty * 4];
            *(float4*)&rb[0] = *(const float4*)&Bs[kk][tx * 4];
            *(float4*)&rb[4] = *(const float4*)&Bs[kk][64 + tx * 4];
            #pragma unroll
            for (int i = 0; i < 8; i++)
                #pragma unroll
                for (int j = 0; j < 8; j++)
                    acc[i][j] = fmaf(ra[i], rb[j], acc[i][j]);
        }
        __syncthreads();
    }

    // Epilogue: bias add + store (float4)
    #pragma unroll
    for (int ih = 0; ih < 2; ih++) {
        #pragma unroll
        for (int i = 0; i < 4; i++) {
            int row = m0 + ih * 64 + ty * 4 + i;
            #pragma unroll
            for (int jh = 0; jh < 2; jh++) {
                int col = n0 + jh * 64 + tx * 4;
                float4 bv = *(const float4*)&bias[col];
                float4 r;
                r.x = acc[ih * 4 + i][jh * 4 + 0] + bv.x;
                r.y = acc[ih * 4 + i][jh * 4 + 1] + bv.y;
                r.z = acc[ih * 4 + i][jh * 4 + 2] + bv.z;
                r.w = acc[ih * 4 + i][jh * 4 + 3] + bv.w;
                *(float4*)&Out[(size_t)row * N + col] = r;
            }
        }
    }
}

// ---------------------------------------------------------------------------
// Flash attention (causal + att_mask), fp32, online softmax.
// One CTA per (q-block of 64 rows, head, batch). K-tiles of 32 rows.
// 256 threads: (tx 0..15, ty 0..15).
//   S compute: thread owns rows ty*4+i (i<4), cols tx*2+j (j<2)
//   softmax:   thread t -> row t>>2, quad lane t&3 covers 8 cols
//   PV:        thread owns rows ty*4+i, d-cols tx*4+j
// ---------------------------------------------------------------------------
#define ABM 64
#define ABN 32

__global__ __launch_bounds__(256)
void attn_kernel(const int* __restrict__ mask, float* __restrict__ out) {
    __shared__ float Qs[ABM][68];     // [row][d], stride 68 keeps float4 alignment
    __shared__ float Ks[ABN][68];
    __shared__ float Vs[ABN][68];
    __shared__ float Ss[ABM][33];     // scores / probabilities
    __shared__ float m_s[ABM], l_s[ABM], al_s[ABM];

    const int qblk = blockIdx.x;
    const int h    = blockIdx.y;
    const int b    = blockIdx.z;
    const int t    = threadIdx.x;
    const int tx   = t & 15;
    const int ty   = t >> 4;
    const float scale = 0.125f;   // 1/sqrt(64)

    const float* Qbase = g_Q + (size_t)b * S_ * D_ + h * DK_;
    const float* Kbase = g_K + (size_t)b * S_ * D_ + h * DK_;
    const float* Vbase = g_V + (size_t)b * S_ * D_ + h * DK_;
    const int*   mrow  = mask + b * S_;

    // Load Q tile: 64x64 floats = 1024 float4, 4 per thread.
    #pragma unroll
    for (int i = 0; i < 4; i++) {
        int idx = t + i * 256;          // 0..1023
        int r   = idx >> 4;
        int d4  = (idx & 15) * 4;
        *(float4*)&Qs[r][d4] =
            *(const float4*)&Qbase[(size_t)(qblk * ABM + r) * D_ + d4];
    }
    if (t < ABM) { m_s[t] = -3.0e38f; l_s[t] = 0.f; }

    float o[4][4];
    #pragma unroll
    for (int i = 0; i < 4; i++)
        #pragma unroll
        for (int j = 0; j < 4; j++) o[i][j] = 0.f;

    const int ntiles = 2 * qblk + 2;   // causal bound: cols <= qblk*64+63

    for (int kt = 0; kt < ntiles; kt++) {
        __syncthreads();   // previous PV done before K/V/S overwrite; also covers Q load
        // Load K & V tiles: 32x64 each = 512 float4, 2 per thread each.
        #pragma unroll
        for (int i = 0; i < 2; i++) {
            int idx = t + i * 256;      // 0..511
            int r   = idx >> 4;
            int d4  = (idx & 15) * 4;
            *(float4*)&Ks[r][d4] =
                *(const float4*)&Kbase[(size_t)(kt * ABN + r) * D_ + d4];
            *(float4*)&Vs[r][d4] =
                *(const float4*)&Vbase[(size_t)(kt * ABN + r) * D_ + d4];
        }
        __syncthreads();

        // S = Q K^T  (rows ty*4+i, cols tx*2+j)
        float sc[4][2];
        #pragma unroll
        for (int i = 0; i < 4; i++) { sc[i][0] = 0.f; sc[i][1] = 0.f; }
        #pragma unroll
        for (int kk = 0; kk < 16; kk++) {
            float4 q4[4], k4[2];
            #pragma unroll
            for (int i = 0; i < 4; i++) q4[i] = *(const float4*)&Qs[ty * 4 + i][kk * 4];
            #pragma unroll
            for (int j = 0; j < 2; j++) k4[j] = *(const float4*)&Ks[tx * 2 + j][kk * 4];
            #pragma unroll
            for (int i = 0; i < 4; i++)
                #pragma unroll
                for (int j = 0; j < 2; j++) {
                    sc[i][j] = fmaf(q4[i].x, k4[j].x, sc[i][j]);
                    sc[i][j] = fmaf(q4[i].y, k4[j].y, sc[i][j]);
                    sc[i][j] = fmaf(q4[i].z, k4[j].z, sc[i][j]);
                    sc[i][j] = fmaf(q4[i].w, k4[j].w, sc[i][j]);
                }
        }
        const int qr0 = qblk * ABM + ty * 4;
        #pragma unroll
        for (int i = 0; i < 4; i++)
            #pragma unroll
            for (int j = 0; j < 2; j++) {
                int c = kt * ABN + tx * 2 + j;
                float v = sc[i][j] * scale;
                if (c > qr0 + i || mrow[c] == 0) v = -1.0e30f;
                Ss[ty * 4 + i][tx * 2 + j] = v;
            }
        __syncthreads();

        // Online softmax update: row = t>>2, quad lane q covers cols q*8..q*8+7
        {
            int row = t >> 2;
            int q   = t & 3;
            float vals[8];
            float mloc = -3.0e38f;
            #pragma unroll
            for (int j = 0; j < 8; j++) {
                vals[j] = Ss[row][q * 8 + j];
                mloc = fmaxf(mloc, vals[j]);
            }
            float m_old = m_s[row];   // read BEFORE quad sync point (no race w/ lane0 write)
            mloc = fmaxf(mloc, __shfl_xor_sync(0xffffffffu, mloc, 1));
            mloc = fmaxf(mloc, __shfl_xor_sync(0xffffffffu, mloc, 2));
            float m_new = fmaxf(m_old, mloc);
            float ssum = 0.f;
            #pragma unroll
            for (int j = 0; j < 8; j++) {
                float p = __expf(vals[j] - m_new);
                Ss[row][q * 8 + j] = p;
                ssum += p;
            }
            ssum += __shfl_xor_sync(0xffffffffu, ssum, 1);
            ssum += __shfl_xor_sync(0xffffffffu, ssum, 2);
            if (q == 0) {
                float alpha = __expf(m_old - m_new);
                l_s[row] = l_s[row] * alpha + ssum;
                m_s[row] = m_new;
                al_s[row] = alpha;
            }
        }
        __syncthreads();

        // O = O*alpha + P @ V   (rows ty*4+i, d-cols tx*4..tx*4+3)
        float al[4];
        #pragma unroll
        for (int i = 0; i < 4; i++) al[i] = al_s[ty * 4 + i];
        #pragma unroll
        for (int i = 0; i < 4; i++)
            #pragma unroll
            for (int j = 0; j < 4; j++) o[i][j] *= al[i];
        #pragma unroll
        for (int k = 0; k < ABN; k++) {
            float4 v4 = *(const float4*)&Vs[k][tx * 4];
            #pragma unroll
            for (int i = 0; i < 4; i++) {
                float p = Ss[ty * 4 + i][k];
                o[i][0] = fmaf(p, v4.x, o[i][0]);
                o[i][1] = fmaf(p, v4.y, o[i][1]);
                o[i][2] = fmaf(p, v4.z, o[i][2]);
                o[i][3] = fmaf(p, v4.w, o[i][3]);
            }
        }
    }

    // Final normalize + store: out[b, row, h*64 + d]
    #pragma unroll
    for (int i = 0; i < 4; i++) {
        float inv = 1.0f / l_s[ty * 4 + i];
        int row = qblk * ABM + ty * 4 + i;
        float4 r;
        r.x = o[i][0] * inv; r.y = o[i][1] * inv;
        r.z = o[i][2] * inv; r.w = o[i][3] * inv;
        *(float4*)&out[(size_t)(b * S_ + row) * D_ + h * DK_ + tx * 4] = r;
    }
}

// ---------------------------------------------------------------------------
// Launch
// inputs (metadata order): query, key, value, att_mask, Wq, bq, Wk, bk, Wv, bv
// ---------------------------------------------------------------------------
extern "C" void kernel_launch(void* const* d_in, const int* in_sizes, int n_in,
                              void* d_out, int out_size) {
    (void)in_sizes; (void)n_in; (void)out_size;
    const float* query = (const float*)d_in[0];
    const float* key   = (const float*)d_in[1];
    const float* value = (const float*)d_in[2];
    const int*   amask = (const int*)  d_in[3];
    const float* Wq = (const float*)d_in[4];
    const float* bq = (const float*)d_in[5];
    const float* Wk = (const float*)d_in[6];
    const float* bk = (const float*)d_in[7];
    const float* Wv = (const float*)d_in[8];
    const float* bv = (const float*)d_in[9];
    float* out = (float*)d_out;

    dim3 gproj(D_ / GBN, M_TOT / GBM, 3);   // (8, 32, 3)
    qkv_proj_kernel<<<gproj, 256>>>(query, key, value, Wq, bq, Wk, bk, Wv, bv);

    dim3 gattn(S_ / ABM, H_, B_);            // (16, 16, 4)
    attn_kernel<<<gattn, 256>>>(amask, out);
}

// round 4
// speedup vs baseline: 1.6341x; 1.6341x over previous
#include <cuda_runtime.h>
#include <cuda_bf16.h>
#include <cstdint>

// Problem constants
#define B_ 4
#define S_ 1024
#define D_ 1024
#define H_ 16
#define DK_ 64
#define M_TOT (B_ * S_)   // 4096

// Scratch for projected Q, K, V (allocation-free rule: __device__ globals)
__device__ float g_Q[M_TOT * D_];
__device__ float g_K[M_TOT * D_];
__device__ float g_V[M_TOT * D_];

// ---------------------------------------------------------------------------
// Small PTX helpers (baseline sm_80+ features only — target is sm_100 BASE,
// no 'a' suffix, so tcgen05/TMEM are unavailable).
// ---------------------------------------------------------------------------
__device__ __forceinline__ uint32_t cvt_tf32(float f) {
    uint32_t r;
    asm("cvt.rna.tf32.f32 %0, %1;" : "=r"(r) : "f"(f));
    return r;
}

__device__ __forceinline__ void cp_async16(void* smem_dst, const void* gmem_src) {
    uint32_t d = (uint32_t)__cvta_generic_to_shared(smem_dst);
    asm volatile("cp.async.ca.shared.global [%0], [%1], 16;"
                 :: "r"(d), "l"(gmem_src) : "memory");
}
#define CP_ASYNC_COMMIT() asm volatile("cp.async.commit_group;" ::: "memory")
#define CP_ASYNC_WAIT1()  asm volatile("cp.async.wait_group 1;" ::: "memory")

// mma.sync m16n8k8 tf32: D(f32) += A(tf32) * B(tf32)
__device__ __forceinline__ void mma_tf32(float c[4], const uint32_t a[4],
                                         const uint32_t b[2]) {
    asm volatile(
        "mma.sync.aligned.m16n8k8.row.col.f32.tf32.tf32.f32 "
        "{%0,%1,%2,%3}, {%4,%5,%6,%7}, {%8,%9}, {%0,%1,%2,%3};"
        : "+f"(c[0]), "+f"(c[1]), "+f"(c[2]), "+f"(c[3])
        : "r"(a[0]), "r"(a[1]), "r"(a[2]), "r"(a[3]), "r"(b[0]), "r"(b[1]));
}

// ---------------------------------------------------------------------------
// Projection GEMM via tf32 tensor cores:
//   Out[M,N] = X[M,K] @ W[N,K]^T + bias,  M=4096 (per z), N=K=1024
// CTA tile 128x128, BK=16, 2-stage cp.async pipeline.
// 8 warps in 2(M) x 4(N); warp tile 64x32.
// SMEM rows padded to 20 floats -> conflict-free fragment loads.
// ---------------------------------------------------------------------------
#define PBM 128
#define PBN 128
#define PBK 16
#define KSTEPS (D_ / PBK)   // 64

__global__ __launch_bounds__(256, 2)
void qkv_proj_mma(const float* __restrict__ Xq,
                  const float* __restrict__ Xk,
                  const float* __restrict__ Xv,
                  const float* __restrict__ Wq, const float* __restrict__ bq,
                  const float* __restrict__ Wk, const float* __restrict__ bk,
                  const float* __restrict__ Wv, const float* __restrict__ bv) {
    __shared__ float As[2][PBM][PBK + 4];   // [stage][m][k], stride 20 floats
    __shared__ float Bs[2][PBN][PBK + 4];   // [stage][n][k]

    const float* X; const float* W; const float* bias; float* Out;
    if (blockIdx.z == 0)      { X = Xq; W = Wq; bias = bq; Out = g_Q; }
    else if (blockIdx.z == 1) { X = Xk; W = Wk; bias = bk; Out = g_K; }
    else                      { X = Xv; W = Wv; bias = bv; Out = g_V; }

    const int t   = threadIdx.x;
    const int wid = t >> 5;
    const int lid = t & 31;
    const int lr  = lid >> 2;      // groupID (0..7)
    const int lc  = lid & 3;       // threadID_in_group (0..3)
    const int wm  = wid & 1;       // warp M block (0..1), 64 rows each
    const int wn  = wid >> 1;      // warp N block (0..3), 32 cols each
    const int m0  = blockIdx.y * PBM;
    const int n0  = blockIdx.x * PBN;

    float acc[4][4][4];            // [mf][nf][c0..c3]
    #pragma unroll
    for (int i = 0; i < 4; i++)
        #pragma unroll
        for (int j = 0; j < 4; j++)
            #pragma unroll
            for (int r = 0; r < 4; r++) acc[i][j][r] = 0.f;

    // Stage loader: 128 rows x 4 chunks(16B) per matrix = 512 jobs each;
    // each thread does 2 A-jobs + 2 B-jobs.
    auto load_stage = [&](int s, int ks) {
        const int k0 = ks * PBK;
        #pragma unroll
        for (int i = 0; i < 2; i++) {
            int job = t + i * 256;          // 0..511
            int row = job >> 2;             // 0..127
            int ch  = (job & 3) * 4;        // float offset 0,4,8,12
            cp_async16(&As[s][row][ch], &X[(size_t)(m0 + row) * D_ + k0 + ch]);
            cp_async16(&Bs[s][row][ch], &W[(size_t)(n0 + row) * D_ + k0 + ch]);
        }
    };

    load_stage(0, 0);
    CP_ASYNC_COMMIT();

    for (int ks = 0; ks < KSTEPS; ks++) {
        const int s = ks & 1;
        if (ks + 1 < KSTEPS) load_stage((ks + 1) & 1, ks + 1);
        CP_ASYNC_COMMIT();
        CP_ASYNC_WAIT1();          // stage s data resident
        __syncthreads();

        #pragma unroll
        for (int kk = 0; kk < PBK; kk += 8) {
            uint32_t a[4][4], b[4][2];
            #pragma unroll
            for (int mf = 0; mf < 4; mf++) {
                int r = wm * 64 + mf * 16 + lr;
                a[mf][0] = cvt_tf32(As[s][r][kk + lc]);
                a[mf][1] = cvt_tf32(As[s][r + 8][kk + lc]);
                a[mf][2] = cvt_tf32(As[s][r][kk + lc + 4]);
                a[mf][3] = cvt_tf32(As[s][r + 8][kk + lc + 4]);
            }
            #pragma unroll
            for (int nf = 0; nf < 4; nf++) {
                int r = wn * 32 + nf * 8 + lr;
                b[nf][0] = cvt_tf32(Bs[s][r][kk + lc]);
                b[nf][1] = cvt_tf32(Bs[s][r][kk + lc + 4]);
            }
            #pragma unroll
            for (int mf = 0; mf < 4; mf++)
                #pragma unroll
                for (int nf = 0; nf < 4; nf++)
                    mma_tf32(acc[mf][nf], a[mf], b[nf]);
        }
        __syncthreads();           // all warps done with stage s before refill
    }

    // Epilogue: c0=(r,2c) c1=(r,2c+1) c2=(r+8,2c) c3=(r+8,2c+1)
    #pragma unroll
    for (int mf = 0; mf < 4; mf++) {
        int row = m0 + wm * 64 + mf * 16 + lr;
        #pragma unroll
        for (int nf = 0; nf < 4; nf++) {
            int col = n0 + wn * 32 + nf * 8 + lc * 2;
            float2 bv2 = *(const float2*)&bias[col];
            float2 r0, r1;
            r0.x = acc[mf][nf][0] + bv2.x;
            r0.y = acc[mf][nf][1] + bv2.y;
            r1.x = acc[mf][nf][2] + bv2.x;
            r1.y = acc[mf][nf][3] + bv2.y;
            *(float2*)&Out[(size_t)row * D_ + col] = r0;
            *(float2*)&Out[(size_t)(row + 8) * D_ + col] = r1;
        }
    }
}

// ---------------------------------------------------------------------------
// Flash attention (causal + att_mask), fp32, online softmax (R1, proven).
// ---------------------------------------------------------------------------
#define ABM 64
#define ABN 32

__global__ __launch_bounds__(256)
void attn_kernel(const int* __restrict__ mask, float* __restrict__ out) {
    __shared__ float Qs[ABM][68];
    __shared__ float Ks[ABN][68];
    __shared__ float Vs[ABN][68];
    __shared__ float Ss[ABM][33];
    __shared__ float m_s[ABM], l_s[ABM], al_s[ABM];

    const int qblk = blockIdx.x;
    const int h    = blockIdx.y;
    const int b    = blockIdx.z;
    const int t    = threadIdx.x;
    const int tx   = t & 15;
    const int ty   = t >> 4;
    const float scale = 0.125f;

    const float* Qbase = g_Q + (size_t)b * S_ * D_ + h * DK_;
    const float* Kbase = g_K + (size_t)b * S_ * D_ + h * DK_;
    const float* Vbase = g_V + (size_t)b * S_ * D_ + h * DK_;
    const int*   mrow  = mask + b * S_;

    #pragma unroll
    for (int i = 0; i < 4; i++) {
        int idx = t + i * 256;
        int r   = idx >> 4;
        int d4  = (idx & 15) * 4;
        *(float4*)&Qs[r][d4] =
            *(const float4*)&Qbase[(size_t)(qblk * ABM + r) * D_ + d4];
    }
    if (t < ABM) { m_s[t] = -3.0e38f; l_s[t] = 0.f; }

    float o[4][4];
    #pragma unroll
    for (int i = 0; i < 4; i++)
        #pragma unroll
        for (int j = 0; j < 4; j++) o[i][j] = 0.f;

    const int ntiles = 2 * qblk + 2;

    for (int kt = 0; kt < ntiles; kt++) {
        __syncthreads();
        #pragma unroll
        for (int i = 0; i < 2; i++) {
            int idx = t + i * 256;
            int r   = idx >> 4;
            int d4  = (idx & 15) * 4;
            *(float4*)&Ks[r][d4] =
                *(const float4*)&Kbase[(size_t)(kt * ABN + r) * D_ + d4];
            *(float4*)&Vs[r][d4] =
                *(const float4*)&Vbase[(size_t)(kt * ABN + r) * D_ + d4];
        }
        __syncthreads();

        float sc[4][2];
        #pragma unroll
        for (int i = 0; i < 4; i++) { sc[i][0] = 0.f; sc[i][1] = 0.f; }
        #pragma unroll
        for (int kk = 0; kk < 16; kk++) {
            float4 q4[4], k4[2];
            #pragma unroll
            for (int i = 0; i < 4; i++) q4[i] = *(const float4*)&Qs[ty * 4 + i][kk * 4];
            #pragma unroll
            for (int j = 0; j < 2; j++) k4[j] = *(const float4*)&Ks[tx * 2 + j][kk * 4];
            #pragma unroll
            for (int i = 0; i < 4; i++)
                #pragma unroll
                for (int j = 0; j < 2; j++) {
                    sc[i][j] = fmaf(q4[i].x, k4[j].x, sc[i][j]);
                    sc[i][j] = fmaf(q4[i].y, k4[j].y, sc[i][j]);
                    sc[i][j] = fmaf(q4[i].z, k4[j].z, sc[i][j]);
                    sc[i][j] = fmaf(q4[i].w, k4[j].w, sc[i][j]);
                }
        }
        const int qr0 = qblk * ABM + ty * 4;
        #pragma unroll
        for (int i = 0; i < 4; i++)
            #pragma unroll
            for (int j = 0; j < 2; j++) {
                int c = kt * ABN + tx * 2 + j;
                float v = sc[i][j] * scale;
                if (c > qr0 + i || mrow[c] == 0) v = -1.0e30f;
                Ss[ty * 4 + i][tx * 2 + j] = v;
            }
        __syncthreads();

        {
            int row = t >> 2;
            int q   = t & 3;
            float vals[8];
            float mloc = -3.0e38f;
            #pragma unroll
            for (int j = 0; j < 8; j++) {
                vals[j] = Ss[row][q * 8 + j];
                mloc = fmaxf(mloc, vals[j]);
            }
            float m_old = m_s[row];
            mloc = fmaxf(mloc, __shfl_xor_sync(0xffffffffu, mloc, 1));
            mloc = fmaxf(mloc, __shfl_xor_sync(0xffffffffu, mloc, 2));
            float m_new = fmaxf(m_old, mloc);
            float ssum = 0.f;
            #pragma unroll
            for (int j = 0; j < 8; j++) {
                float p = __expf(vals[j] - m_new);
                Ss[row][q * 8 + j] = p;
                ssum += p;
            }
            ssum += __shfl_xor_sync(0xffffffffu, ssum, 1);
            ssum += __shfl_xor_sync(0xffffffffu, ssum, 2);
            if (q == 0) {
                float alpha = __expf(m_old - m_new);
                l_s[row] = l_s[row] * alpha + ssum;
                m_s[row] = m_new;
                al_s[row] = alpha;
            }
        }
        __syncthreads();

        float al[4];
        #pragma unroll
        for (int i = 0; i < 4; i++) al[i] = al_s[ty * 4 + i];
        #pragma unroll
        for (int i = 0; i < 4; i++)
            #pragma unroll
            for (int j = 0; j < 4; j++) o[i][j] *= al[i];
        #pragma unroll
        for (int k = 0; k < ABN; k++) {
            float4 v4 = *(const float4*)&Vs[k][tx * 4];
            #pragma unroll
            for (int i = 0; i < 4; i++) {
                float p = Ss[ty * 4 + i][k];
                o[i][0] = fmaf(p, v4.x, o[i][0]);
                o[i][1] = fmaf(p, v4.y, o[i][1]);
                o[i][2] = fmaf(p, v4.z, o[i][2]);
                o[i][3] = fmaf(p, v4.w, o[i][3]);
            }
        }
    }

    #pragma unroll
    for (int i = 0; i < 4; i++) {
        float inv = 1.0f / l_s[ty * 4 + i];
        int row = qblk * ABM + ty * 4 + i;
        float4 r;
        r.x = o[i][0] * inv; r.y = o[i][1] * inv;
        r.z = o[i][2] * inv; r.w = o[i][3] * inv;
        *(float4*)&out[(size_t)(b * S_ + row) * D_ + h * DK_ + tx * 4] = r;
    }
}

// ---------------------------------------------------------------------------
// Launch
// inputs: query, key, value, att_mask, Wq, bq, Wk, bk, Wv, bv
// ---------------------------------------------------------------------------
extern "C" void kernel_launch(void* const* d_in, const int* in_sizes, int n_in,
                              void* d_out, int out_size) {
    (void)in_sizes; (void)n_in; (void)out_size;
    const float* query = (const float*)d_in[0];
    const float* key   = (const float*)d_in[1];
    const float* value = (const float*)d_in[2];
    const int*   amask = (const int*)  d_in[3];
    const float* Wq = (const float*)d_in[4];
    const float* bq = (const float*)d_in[5];
    const float* Wk = (const float*)d_in[6];
    const float* bk = (const float*)d_in[7];
    const float* Wv = (const float*)d_in[8];
    const float* bv = (const float*)d_in[9];
    float* out = (float*)d_out;

    dim3 gproj(D_ / PBN, M_TOT / PBM, 3);   // (8, 32, 3)
    qkv_proj_mma<<<gproj, 256>>>(query, key, value, Wq, bq, Wk, bk, Wv, bv);

    dim3 gattn(S_ / ABM, H_, B_);            // (16, 16, 4)
    attn_kernel<<<gattn, 256>>>(amask, out);
}

// round 5
// speedup vs baseline: 2.7848x; 1.7042x over previous
#include <cuda_runtime.h>
#include <cuda_bf16.h>
#include <cstdint>

// Problem constants
#define B_ 4
#define S_ 1024
#define D_ 1024
#define H_ 16
#define DK_ 64
#define M_TOT (B_ * S_)   // 4096

// Scratch for projected Q, K, V (allocation-free rule: __device__ globals)
__device__ float g_Q[M_TOT * D_];
__device__ float g_K[M_TOT * D_];
__device__ float g_V[M_TOT * D_];

// ---------------------------------------------------------------------------
// PTX helpers (baseline sm_80+ features only — target is sm_100 BASE).
// ---------------------------------------------------------------------------
__device__ __forceinline__ uint32_t cvt_tf32(float f) {
    uint32_t r;
    asm("cvt.rna.tf32.f32 %0, %1;" : "=r"(r) : "f"(f));
    return r;
}

__device__ __forceinline__ void cp_async16(void* smem_dst, const void* gmem_src) {
    uint32_t d = (uint32_t)__cvta_generic_to_shared(smem_dst);
    asm volatile("cp.async.ca.shared.global [%0], [%1], 16;"
                 :: "r"(d), "l"(gmem_src) : "memory");
}
#define CP_ASYNC_COMMIT() asm volatile("cp.async.commit_group;" ::: "memory")
#define CP_ASYNC_WAIT1()  asm volatile("cp.async.wait_group 1;" ::: "memory")

// mma.sync m16n8k8 tf32
__device__ __forceinline__ void mma_tf32(float c[4], const uint32_t a[4],
                                         const uint32_t b[2]) {
    asm volatile(
        "mma.sync.aligned.m16n8k8.row.col.f32.tf32.tf32.f32 "
        "{%0,%1,%2,%3}, {%4,%5,%6,%7}, {%8,%9}, {%0,%1,%2,%3};"
        : "+f"(c[0]), "+f"(c[1]), "+f"(c[2]), "+f"(c[3])
        : "r"(a[0]), "r"(a[1]), "r"(a[2]), "r"(a[3]), "r"(b[0]), "r"(b[1]));
}

// mma.sync m16n8k16 bf16
__device__ __forceinline__ void mma_bf16(float c[4],
                                         uint32_t a0, uint32_t a1, uint32_t a2, uint32_t a3,
                                         uint32_t b0, uint32_t b1) {
    asm volatile(
        "mma.sync.aligned.m16n8k16.row.col.f32.bf16.bf16.f32 "
        "{%0,%1,%2,%3}, {%4,%5,%6,%7}, {%8,%9}, {%0,%1,%2,%3};"
        : "+f"(c[0]), "+f"(c[1]), "+f"(c[2]), "+f"(c[3])
        : "r"(a0), "r"(a1), "r"(a2), "r"(a3), "r"(b0), "r"(b1));
}

__device__ __forceinline__ void ldmatrix_x4_trans(uint32_t& r0, uint32_t& r1,
                                                  uint32_t& r2, uint32_t& r3,
                                                  uint32_t smem_addr) {
    asm volatile("ldmatrix.sync.aligned.m8n8.x4.trans.shared.b16 "
                 "{%0,%1,%2,%3}, [%4];"
                 : "=r"(r0), "=r"(r1), "=r"(r2), "=r"(r3) : "r"(smem_addr));
}

__device__ __forceinline__ uint32_t packbf(float a, float b) {
    __nv_bfloat162 t = __floats2bfloat162_rn(a, b);
    return *reinterpret_cast<uint32_t*>(&t);
}
__device__ __forceinline__ float residf(float a) {
    return a - __bfloat162float(__float2bfloat16(a));
}
__device__ __forceinline__ uint32_t lds_u32(const ushort* p, int elem) {
    return *reinterpret_cast<const uint32_t*>(p + elem);
}
// split a,b into bf16 hi/lo pairs and store as packed u32 at elem (even)
__device__ __forceinline__ void split_store(ushort* h, ushort* l, int elem,
                                            float a, float b) {
    *reinterpret_cast<uint32_t*>(h + elem) = packbf(a, b);
    *reinterpret_cast<uint32_t*>(l + elem) = packbf(residf(a), residf(b));
}

// ---------------------------------------------------------------------------
// Projection GEMM via tf32 tensor cores (unchanged from R4, proven 226us):
//   Out[M,N] = X[M,K] @ W[N,K]^T + bias
// ---------------------------------------------------------------------------
#define PBM 128
#define PBN 128
#define PBK 16
#define KSTEPS (D_ / PBK)   // 64

__global__ __launch_bounds__(256, 2)
void qkv_proj_mma(const float* __restrict__ Xq,
                  const float* __restrict__ Xk,
                  const float* __restrict__ Xv,
                  const float* __restrict__ Wq, const float* __restrict__ bq,
                  const float* __restrict__ Wk, const float* __restrict__ bk,
                  const float* __restrict__ Wv, const float* __restrict__ bv) {
    __shared__ float As[2][PBM][PBK + 4];
    __shared__ float Bs[2][PBN][PBK + 4];

    const float* X; const float* W; const float* bias; float* Out;
    if (blockIdx.z == 0)      { X = Xq; W = Wq; bias = bq; Out = g_Q; }
    else if (blockIdx.z == 1) { X = Xk; W = Wk; bias = bk; Out = g_K; }
    else                      { X = Xv; W = Wv; bias = bv; Out = g_V; }

    const int t   = threadIdx.x;
    const int wid = t >> 5;
    const int lid = t & 31;
    const int lr  = lid >> 2;
    const int lc  = lid & 3;
    const int wm  = wid & 1;
    const int wn  = wid >> 1;
    const int m0  = blockIdx.y * PBM;
    const int n0  = blockIdx.x * PBN;

    float acc[4][4][4];
    #pragma unroll
    for (int i = 0; i < 4; i++)
        #pragma unroll
        for (int j = 0; j < 4; j++)
            #pragma unroll
            for (int r = 0; r < 4; r++) acc[i][j][r] = 0.f;

    auto load_stage = [&](int s, int ks) {
        const int k0 = ks * PBK;
        #pragma unroll
        for (int i = 0; i < 2; i++) {
            int job = t + i * 256;
            int row = job >> 2;
            int ch  = (job & 3) * 4;
            cp_async16(&As[s][row][ch], &X[(size_t)(m0 + row) * D_ + k0 + ch]);
            cp_async16(&Bs[s][row][ch], &W[(size_t)(n0 + row) * D_ + k0 + ch]);
        }
    };

    load_stage(0, 0);
    CP_ASYNC_COMMIT();

    for (int ks = 0; ks < KSTEPS; ks++) {
        const int s = ks & 1;
        if (ks + 1 < KSTEPS) load_stage((ks + 1) & 1, ks + 1);
        CP_ASYNC_COMMIT();
        CP_ASYNC_WAIT1();
        __syncthreads();

        #pragma unroll
        for (int kk = 0; kk < PBK; kk += 8) {
            uint32_t a[4][4], b[4][2];
            #pragma unroll
            for (int mf = 0; mf < 4; mf++) {
                int r = wm * 64 + mf * 16 + lr;
                a[mf][0] = cvt_tf32(As[s][r][kk + lc]);
                a[mf][1] = cvt_tf32(As[s][r + 8][kk + lc]);
                a[mf][2] = cvt_tf32(As[s][r][kk + lc + 4]);
                a[mf][3] = cvt_tf32(As[s][r + 8][kk + lc + 4]);
            }
            #pragma unroll
            for (int nf = 0; nf < 4; nf++) {
                int r = wn * 32 + nf * 8 + lr;
                b[nf][0] = cvt_tf32(Bs[s][r][kk + lc]);
                b[nf][1] = cvt_tf32(Bs[s][r][kk + lc + 4]);
            }
            #pragma unroll
            for (int mf = 0; mf < 4; mf++)
                #pragma unroll
                for (int nf = 0; nf < 4; nf++)
                    mma_tf32(acc[mf][nf], a[mf], b[nf]);
        }
        __syncthreads();
    }

    #pragma unroll
    for (int mf = 0; mf < 4; mf++) {
        int row = m0 + wm * 64 + mf * 16 + lr;
        #pragma unroll
        for (int nf = 0; nf < 4; nf++) {
            int col = n0 + wn * 32 + nf * 8 + lc * 2;
            float2 bv2 = *(const float2*)&bias[col];
            float2 r0, r1;
            r0.x = acc[mf][nf][0] + bv2.x;
            r0.y = acc[mf][nf][1] + bv2.y;
            r1.x = acc[mf][nf][2] + bv2.x;
            r1.y = acc[mf][nf][3] + bv2.y;
            *(float2*)&Out[(size_t)row * D_ + col] = r0;
            *(float2*)&Out[(size_t)(row + 8) * D_ + col] = r1;
        }
    }
}

// ---------------------------------------------------------------------------
// Flash attention with bf16 MMA + hi/lo compensation.
// CTA: 128 q-rows x head. 8 warps, warp w owns rows w*16..w*16+15 (all 64 cols)
// -> softmax fully warp-local. K-tiles of 64 cols.
//   S = (Qh+Ql)(Kh+Kl)^T ~= Qh*Kh + Qh*Kl + Ql*Kh   (3 bf16 mma passes)
//   O += (Ph+Pl)(Vh+Vl)  ~= Ph*Vh + Ph*Vl + Pl*Vh
// P stays in registers (C-frag layout == A-frag layout for m16n8k16).
// V B-fragments via ldmatrix.x4.trans from naturally-stored [seq][dk] tile.
// ---------------------------------------------------------------------------
#define QSTR 72
#define KSTR 72
#define VSTR 72
// smem byte offsets
#define SM_QH 0
#define SM_QL 18432
#define SM_KH 36864
#define SM_KL 46080
#define SM_VH 55296
#define SM_VL 64512
#define SM_MK 73728
#define ATTN_SMEM 73984

__global__ __launch_bounds__(256, 2)
void attn_mma(const int* __restrict__ mask, float* __restrict__ out) {
    extern __shared__ char sm[];
    ushort* Qh = (ushort*)(sm + SM_QH);
    ushort* Ql = (ushort*)(sm + SM_QL);
    ushort* Kh = (ushort*)(sm + SM_KH);
    ushort* Kl = (ushort*)(sm + SM_KL);
    ushort* Vh = (ushort*)(sm + SM_VH);
    ushort* Vl = (ushort*)(sm + SM_VL);
    int*    mk = (int*)   (sm + SM_MK);

    const int qb = (int)(gridDim.x - 1) - (int)blockIdx.x;   // heavy blocks first
    const int h  = blockIdx.y;
    const int b  = blockIdx.z;
    const int q0 = qb * 128;
    const int t  = threadIdx.x;
    const int w  = t >> 5;
    const int lid = t & 31;
    const int lr = lid >> 2;
    const int lc = lid & 3;

    const float* Qbase = g_Q + (size_t)b * S_ * D_ + h * DK_;
    const float* Kbase = g_K + (size_t)b * S_ * D_ + h * DK_;
    const float* Vbase = g_V + (size_t)b * S_ * D_ + h * DK_;
    const int*   mrow  = mask + b * S_;

    const uint32_t vh32 = (uint32_t)__cvta_generic_to_shared(Vh);
    const uint32_t vl32 = (uint32_t)__cvta_generic_to_shared(Vl);

    // Load + split Q tile (128 x 64): thread t -> row t>>1, half (t&1)*32.
    {
        int row  = t >> 1;
        int half = (t & 1) * 32;
        const float* src = Qbase + (size_t)(q0 + row) * D_ + half;
        #pragma unroll
        for (int i = 0; i < 8; i++) {
            float4 v = *(const float4*)&src[i * 4];
            int e = row * QSTR + half + i * 4;
            split_store(Qh, Ql, e,     v.x, v.y);
            split_store(Qh, Ql, e + 2, v.z, v.w);
        }
    }

    float o[8][4];
    #pragma unroll
    for (int i = 0; i < 8; i++)
        #pragma unroll
        for (int j = 0; j < 4; j++) o[i][j] = 0.f;
    float m0 = -1.0e30f, m1 = -1.0e30f, l0 = 0.f, l1 = 0.f;

    const int gr0 = q0 + w * 16 + lr;   // global q row (low)
    const int ntiles = 2 * qb + 2;

    for (int kt = 0; kt < ntiles; kt++) {
        if (kt) __syncthreads();   // prior tile's reads done before overwrite
        // Load + split K and V tiles (64 x 64 each)
        {
            int r = t >> 2, seg = t & 3;
            const float* Kt = Kbase + (size_t)(kt * 64 + r) * D_ + seg * 16;
            const float* Vt = Vbase + (size_t)(kt * 64 + r) * D_ + seg * 16;
            #pragma unroll
            for (int c4 = 0; c4 < 4; c4++) {
                float4 kv = *(const float4*)&Kt[c4 * 4];
                int ek = r * KSTR + seg * 16 + c4 * 4;
                split_store(Kh, Kl, ek,     kv.x, kv.y);
                split_store(Kh, Kl, ek + 2, kv.z, kv.w);
                float4 vv = *(const float4*)&Vt[c4 * 4];
                int ev = r * VSTR + seg * 16 + c4 * 4;
                split_store(Vh, Vl, ev,     vv.x, vv.y);
                split_store(Vh, Vl, ev + 2, vv.z, vv.w);
            }
            if (t < 64) mk[t] = mrow[kt * 64 + t];
        }
        __syncthreads();

        // Warp fully above the diagonal on this tile? (covers also Q-load sync)
        bool active = (kt * 64 <= q0 + w * 16 + 15);
        if (active) {
            // ---- S = Q K^T (3-pass bf16) ----
            float s[8][4];
            #pragma unroll
            for (int i = 0; i < 8; i++)
                #pragma unroll
                for (int j = 0; j < 4; j++) s[i][j] = 0.f;

            #pragma unroll
            for (int ks = 0; ks < 4; ks++) {
                int arow = w * 16 + lr;
                int ko   = ks * 16 + 2 * lc;
                uint32_t ah0 = lds_u32(Qh, arow * QSTR + ko);
                uint32_t ah1 = lds_u32(Qh, (arow + 8) * QSTR + ko);
                uint32_t ah2 = lds_u32(Qh, arow * QSTR + ko + 8);
                uint32_t ah3 = lds_u32(Qh, (arow + 8) * QSTR + ko + 8);
                uint32_t al0 = lds_u32(Ql, arow * QSTR + ko);
                uint32_t al1 = lds_u32(Ql, (arow + 8) * QSTR + ko);
                uint32_t al2 = lds_u32(Ql, arow * QSTR + ko + 8);
                uint32_t al3 = lds_u32(Ql, (arow + 8) * QSTR + ko + 8);
                #pragma unroll
                for (int nf = 0; nf < 8; nf++) {
                    int br = nf * 8 + lr;
                    uint32_t bh0 = lds_u32(Kh, br * KSTR + ko);
                    uint32_t bh1 = lds_u32(Kh, br * KSTR + ko + 8);
                    uint32_t bl0 = lds_u32(Kl, br * KSTR + ko);
                    uint32_t bl1 = lds_u32(Kl, br * KSTR + ko + 8);
                    mma_bf16(s[nf], ah0, ah1, ah2, ah3, bh0, bh1);
                    mma_bf16(s[nf], ah0, ah1, ah2, ah3, bl0, bl1);
                    mma_bf16(s[nf], al0, al1, al2, al3, bh0, bh1);
                }
            }

            // ---- scale + mask ----
            const bool diag = (kt >= 2 * qb);
            #pragma unroll
            for (int nf = 0; nf < 8; nf++) {
                int ci  = nf * 8 + 2 * lc;
                int c0  = kt * 64 + ci, c1 = c0 + 1;
                int mv0 = mk[ci], mv1 = mk[ci + 1];
                float v;
                v = s[nf][0] * 0.125f;
                if ((diag && c0 > gr0) || mv0 == 0) v = -1.0e30f;
                s[nf][0] = v;
                v = s[nf][1] * 0.125f;
                if ((diag && c1 > gr0) || mv1 == 0) v = -1.0e30f;
                s[nf][1] = v;
                v = s[nf][2] * 0.125f;
                if ((diag && c0 > gr0 + 8) || mv0 == 0) v = -1.0e30f;
                s[nf][2] = v;
                v = s[nf][3] * 0.125f;
                if ((diag && c1 > gr0 + 8) || mv1 == 0) v = -1.0e30f;
                s[nf][3] = v;
            }

            // ---- online softmax (warp-local; rows split across quad lanes) ----
            float mx0 = -1.0e30f, mx1 = -1.0e30f;
            #pragma unroll
            for (int nf = 0; nf < 8; nf++) {
                mx0 = fmaxf(mx0, fmaxf(s[nf][0], s[nf][1]));
                mx1 = fmaxf(mx1, fmaxf(s[nf][2], s[nf][3]));
            }
            mx0 = fmaxf(mx0, __shfl_xor_sync(0xffffffffu, mx0, 1));
            mx0 = fmaxf(mx0, __shfl_xor_sync(0xffffffffu, mx0, 2));
            mx1 = fmaxf(mx1, __shfl_xor_sync(0xffffffffu, mx1, 1));
            mx1 = fmaxf(mx1, __shfl_xor_sync(0xffffffffu, mx1, 2));
            float mn0 = fmaxf(m0, mx0), mn1 = fmaxf(m1, mx1);
            float alpha0 = __expf(m0 - mn0), alpha1 = __expf(m1 - mn1);
            m0 = mn0; m1 = mn1;

            float sum0 = 0.f, sum1 = 0.f;
            #pragma unroll
            for (int nf = 0; nf < 8; nf++) {
                float p;
                p = (s[nf][0] > -9.0e29f) ? __expf(s[nf][0] - mn0) : 0.f;
                s[nf][0] = p; sum0 += p;
                p = (s[nf][1] > -9.0e29f) ? __expf(s[nf][1] - mn0) : 0.f;
                s[nf][1] = p; sum0 += p;
                p = (s[nf][2] > -9.0e29f) ? __expf(s[nf][2] - mn1) : 0.f;
                s[nf][2] = p; sum1 += p;
                p = (s[nf][3] > -9.0e29f) ? __expf(s[nf][3] - mn1) : 0.f;
                s[nf][3] = p; sum1 += p;
            }
            sum0 += __shfl_xor_sync(0xffffffffu, sum0, 1);
            sum0 += __shfl_xor_sync(0xffffffffu, sum0, 2);
            sum1 += __shfl_xor_sync(0xffffffffu, sum1, 1);
            sum1 += __shfl_xor_sync(0xffffffffu, sum1, 2);
            l0 = l0 * alpha0 + sum0;
            l1 = l1 * alpha1 + sum1;

            #pragma unroll
            for (int nf = 0; nf < 8; nf++) {
                o[nf][0] *= alpha0; o[nf][1] *= alpha0;
                o[nf][2] *= alpha1; o[nf][3] *= alpha1;
            }

            // ---- O += P V (3-pass bf16); P packed from registers ----
            #pragma unroll
            for (int ks = 0; ks < 4; ks++) {
                uint32_t ph0 = packbf(s[2*ks][0],   s[2*ks][1]);
                uint32_t ph1 = packbf(s[2*ks][2],   s[2*ks][3]);
                uint32_t ph2 = packbf(s[2*ks+1][0], s[2*ks+1][1]);
                uint32_t ph3 = packbf(s[2*ks+1][2], s[2*ks+1][3]);
                uint32_t pl0 = packbf(residf(s[2*ks][0]),   residf(s[2*ks][1]));
                uint32_t pl1 = packbf(residf(s[2*ks][2]),   residf(s[2*ks][3]));
                uint32_t pl2 = packbf(residf(s[2*ks+1][0]), residf(s[2*ks+1][1]));
                uint32_t pl3 = packbf(residf(s[2*ks+1][2]), residf(s[2*ks+1][3]));
                // ldmatrix.trans lane addressing
                int g = lid >> 3, lrow = lid & 7;
                #pragma unroll
                for (int nfp = 0; nfp < 4; nfp++) {
                    uint32_t offB = (uint32_t)((ks * 16 + (g & 1) * 8 + lrow) * VSTR
                                               + nfp * 16 + (g >> 1) * 8) * 2;
                    uint32_t bh0, bh1, bh2, bh3, bl0, bl1, bl2, bl3;
                    ldmatrix_x4_trans(bh0, bh1, bh2, bh3, vh32 + offB);
                    ldmatrix_x4_trans(bl0, bl1, bl2, bl3, vl32 + offB);
                    mma_bf16(o[2*nfp],   ph0, ph1, ph2, ph3, bh0, bh1);
                    mma_bf16(o[2*nfp],   ph0, ph1, ph2, ph3, bl0, bl1);
                    mma_bf16(o[2*nfp],   pl0, pl1, pl2, pl3, bh0, bh1);
                    mma_bf16(o[2*nfp+1], ph0, ph1, ph2, ph3, bh2, bh3);
                    mma_bf16(o[2*nfp+1], ph0, ph1, ph2, ph3, bl2, bl3);
                    mma_bf16(o[2*nfp+1], pl0, pl1, pl2, pl3, bh2, bh3);
                }
            }
        }
    }

    // ---- epilogue: normalize + store ----
    float inv0 = 1.0f / l0, inv1 = 1.0f / l1;
    #pragma unroll
    for (int nf = 0; nf < 8; nf++) {
        int col = h * DK_ + nf * 8 + 2 * lc;
        float2 r0, r1;
        r0.x = o[nf][0] * inv0; r0.y = o[nf][1] * inv0;
        r1.x = o[nf][2] * inv1; r1.y = o[nf][3] * inv1;
        *(float2*)&out[(size_t)(b * S_ + gr0) * D_ + col] = r0;
        *(float2*)&out[(size_t)(b * S_ + gr0 + 8) * D_ + col] = r1;
    }
}

// ---------------------------------------------------------------------------
// Launch
// inputs: query, key, value, att_mask, Wq, bq, Wk, bk, Wv, bv
// ---------------------------------------------------------------------------
extern "C" void kernel_launch(void* const* d_in, const int* in_sizes, int n_in,
                              void* d_out, int out_size) {
    (void)in_sizes; (void)n_in; (void)out_size;
    const float* query = (const float*)d_in[0];
    const float* key   = (const float*)d_in[1];
    const float* value = (const float*)d_in[2];
    const int*   amask = (const int*)  d_in[3];
    const float* Wq = (const float*)d_in[4];
    const float* bq = (const float*)d_in[5];
    const float* Wk = (const float*)d_in[6];
    const float* bk = (const float*)d_in[7];
    const float* Wv = (const float*)d_in[8];
    const float* bv = (const float*)d_in[9];
    float* out = (float*)d_out;

    dim3 gproj(D_ / PBN, M_TOT / PBM, 3);   // (8, 32, 3)
    qkv_proj_mma<<<gproj, 256>>>(query, key, value, Wq, bq, Wk, bk, Wv, bv);

    cudaFuncSetAttribute(attn_mma, cudaFuncAttributeMaxDynamicSharedMemorySize,
                         ATTN_SMEM);
    dim3 gattn(S_ / 128, H_, B_);            // (8, 16, 4)
    attn_mma<<<gattn, 256, ATTN_SMEM>>>(amask, out);
}